// round 2
// baseline (speedup 1.0000x reference)
#include <cuda_runtime.h>
#include <cuda_bf16.h>

#define NTHR 128
#define NH   50
#define NNEG 10
#define EDIM 128
#define EV4  32          // EDIM/4
#define EPS  1e-6f

__device__ __forceinline__ float wredsum(float v) {
#pragma unroll
    for (int o = 16; o; o >>= 1) v += __shfl_xor_sync(0xffffffffu, v, o);
    return v;
}
__device__ __forceinline__ float wredmax(float v) {
#pragma unroll
    for (int o = 16; o; o >>= 1) v = fmaxf(v, __shfl_xor_sync(0xffffffffu, v, o));
    return v;
}
__device__ __forceinline__ float dot4(float4 a, float4 b) {
    return a.x * b.x + a.y * b.y + a.z * b.z + a.w * b.w;
}

__global__ __launch_bounds__(NTHR) void htne_kernel(
    const int*   __restrict__ s_nodes,   // [B,1]
    const int*   __restrict__ t_nodes,   // [B,1]
    const float* __restrict__ t_times,   // [B,1]
    const int*   __restrict__ h_nodes,   // [B,H]
    const float* __restrict__ h_times,   // [B,H]
    const float* __restrict__ h_mask,    // [B,H]
    const int*   __restrict__ n_nodes,   // [B,N]
    const float* __restrict__ emb,       // [V,E]
    const float* __restrict__ delta_w,   // [V,1]
    float*       __restrict__ out)       // [B]
{
    const int b    = blockIdx.x;
    const int tid  = threadIdx.x;
    const int wid  = tid >> 5;
    const int lane = tid & 31;

    __shared__ float4 his_s[NH][EV4];       // 25.6 KB
    __shared__ float4 neg_s[NNEG][EV4];     // 5 KB
    __shared__ float4 src_s[EV4];
    __shared__ float4 tar_s[EV4];
    __shared__ float  hbar_s[EDIM];
    __shared__ float  hsq_s[NH], sh_s[NH], th_s[NH], w_s[NH];
    __shared__ float  nterm_s[NNEG];
    __shared__ float  sc_ss, sc_tt, sc_st, sc_W, sc_C, sc_P, sc_invS;

    const float4* emb4 = (const float4*)emb;
    const int sidx = s_nodes[b];
    const int tidx = t_nodes[b];

    // ---- gather all embeddings into smem (LDG.128, coalesced per row) ----
    if (wid == 0) src_s[lane] = emb4[(size_t)sidx * EV4 + lane];
    if (wid == 1) tar_s[lane] = emb4[(size_t)tidx * EV4 + lane];
#pragma unroll
    for (int n = wid; n < NNEG; n += 4)
        neg_s[n][lane] = emb4[(size_t)n_nodes[b * NNEG + n] * EV4 + lane];
    for (int h = wid; h < NH; h += 4)
        his_s[h][lane] = emb4[(size_t)h_nodes[b * NH + h] * EV4 + lane];
    __syncthreads();

    const float4 s4 = src_s[lane];
    const float4 t4 = tar_s[lane];

    // ---- src/tar scalars (warp 0) ----
    if (wid == 0) {
        float ss = wredsum(dot4(s4, s4));
        float tt = wredsum(dot4(t4, t4));
        float st = wredsum(dot4(s4, t4));
        if (lane == 0) { sc_ss = ss; sc_tt = tt; sc_st = st; }
    }

    // ---- per-history: h^2, s.h, t.h in one pass ----
    for (int h = wid; h < NH; h += 4) {
        const float4 h4 = his_s[h][lane];
        float hh = wredsum(dot4(h4, h4));
        float sh = wredsum(dot4(s4, h4));
        float th = wredsum(dot4(t4, h4));
        if (lane == 0) { hsq_s[h] = hh; sh_s[h] = sh; th_s[h] = th; }
    }
    __syncthreads();

    // ---- softmax + decay + weighted scalar reductions (warp 0) ----
    if (wid == 0) {
        const float src_sq = sc_ss, tar_sq = sc_tt;
        const float delta  = delta_w[sidx];
        const float ttime  = t_times[b];

        float logit[2], pal[2], dm[2];   // 2 h per lane: h = lane, lane+32
        float m = -1e30f;
#pragma unroll
        for (int k = 0; k < 2; k++) {
            const int h = lane + 32 * k;
            if (h < NH) {
                logit[k] = -(src_sq + hsq_s[h] - 2.0f * sh_s[h]);
                pal[k]   = -(tar_sq + hsq_s[h] - 2.0f * th_s[h]);
                const float dt = fabsf(ttime - h_times[b * NH + h]);
                dm[k] = expf(delta * dt) * h_mask[b * NH + h];
                m = fmaxf(m, logit[k]);
            }
        }
        m = wredmax(m);

        float S = 0.f, Wn = 0.f, Cn = 0.f, Pn = 0.f;
#pragma unroll
        for (int k = 0; k < 2; k++) {
            const int h = lane + 32 * k;
            if (h < NH) {
                const float e = expf(logit[k] - m);   // unnormalized attention
                const float w = e * dm[k];            // unnormalized weight
                w_s[h] = w;
                S  += e;
                Wn += w;
                Cn += w * hsq_s[h];
                Pn += w * pal[k];
            }
        }
        S  = wredsum(S);
        Wn = wredsum(Wn);
        Cn = wredsum(Cn);
        Pn = wredsum(Pn);
        if (lane == 0) {
            const float invS = 1.0f / S;
            sc_invS = invS;
            sc_W = Wn * invS;
            sc_C = Cn * invS;
            sc_P = Pn * invS;
        }
    }
    __syncthreads();

    // ---- hbar[e] = (1/S) * sum_h w[h] * his[h][e] ----
    {
        const float* hisf = (const float*)his_s;
        float acc = 0.f;
#pragma unroll 10
        for (int h = 0; h < NH; h++)
            acc += w_s[h] * hisf[h * EDIM + tid];
        hbar_s[tid] = acc * sc_invS;
    }
    __syncthreads();

    // ---- per-negative: n^2, s.n, hbar.n ----
    {
        const float4 hb4 = ((const float4*)hbar_s)[lane];
#pragma unroll
        for (int n = wid; n < NNEG; n += 4) {
            const float4 n4 = neg_s[n][lane];
            float nn = wredsum(dot4(n4, n4));
            float sn = wredsum(dot4(s4, n4));
            float hn = wredsum(dot4(hb4, n4));
            if (lane == 0) {
                const float n_mu = -(sc_ss + nn - 2.0f * sn);
                const float nl   = n_mu - sc_C - sc_W * nn + 2.0f * hn;
                // log(sigmoid(-nl) + eps)
                nterm_s[n] = logf(1.0f / (1.0f + expf(nl)) + EPS);
            }
        }
    }
    __syncthreads();

    // ---- final combine ----
    if (tid == 0) {
        const float p_mu     = -(sc_ss + sc_tt - 2.0f * sc_st);
        const float p_lambda = p_mu + sc_P;
        const float pos_loss = -logf(1.0f / (1.0f + expf(-p_lambda)) + EPS);
        float neg_loss = 0.f;
#pragma unroll
        for (int n = 0; n < NNEG; n++) neg_loss += nterm_s[n];
        out[b] = pos_loss - neg_loss;
    }
}

extern "C" void kernel_launch(void* const* d_in, const int* in_sizes, int n_in,
                              void* d_out, int out_size)
{
    const int*   s_nodes = (const int*)  d_in[0];
    const int*   t_nodes = (const int*)  d_in[1];
    const float* t_times = (const float*)d_in[2];
    const int*   h_nodes = (const int*)  d_in[3];
    const float* h_times = (const float*)d_in[4];
    const float* h_mask  = (const float*)d_in[5];
    const int*   n_nodes = (const int*)  d_in[6];
    const float* emb     = (const float*)d_in[7];
    const float* delta_w = (const float*)d_in[8];
    float*       out     = (float*)d_out;

    const int B = in_sizes[0];   // 4096
    htne_kernel<<<B, NTHR>>>(s_nodes, t_nodes, t_times, h_nodes, h_times,
                             h_mask, n_nodes, emb, delta_w, out);
}

// round 3
// speedup vs baseline: 1.1625x; 1.1625x over previous
#include <cuda_runtime.h>
#include <cuda_bf16.h>

#define NTHR  256
#define NWARP 8
#define NH    50
#define NNEG  10
#define EDIM  128
#define EV4   32          // EDIM/4
#define EPS   1e-6f

__device__ __forceinline__ float wredsum(float v) {
#pragma unroll
    for (int o = 16; o; o >>= 1) v += __shfl_xor_sync(0xffffffffu, v, o);
    return v;
}
__device__ __forceinline__ float wredmax(float v) {
#pragma unroll
    for (int o = 16; o; o >>= 1) v = fmaxf(v, __shfl_xor_sync(0xffffffffu, v, o));
    return v;
}
__device__ __forceinline__ float dot4(float4 a, float4 b) {
    return a.x * b.x + a.y * b.y + a.z * b.z + a.w * b.w;
}

__global__ __launch_bounds__(NTHR) void htne_kernel(
    const int*   __restrict__ s_nodes,   // [B,1]
    const int*   __restrict__ t_nodes,   // [B,1]
    const float* __restrict__ t_times,   // [B,1]
    const int*   __restrict__ h_nodes,   // [B,H]
    const float* __restrict__ h_times,   // [B,H]
    const float* __restrict__ h_mask,    // [B,H]
    const int*   __restrict__ n_nodes,   // [B,N]
    const float* __restrict__ emb,       // [V,E]
    const float* __restrict__ delta_w,   // [V,1]
    float*       __restrict__ out)       // [B]
{
    const int b    = blockIdx.x;
    const int tid  = threadIdx.x;
    const int wid  = tid >> 5;
    const int lane = tid & 31;

    __shared__ float4 his_s[NH][EV4];          // 25.6 KB
    __shared__ float4 src_s[EV4];
    __shared__ float4 tar_s[EV4];
    __shared__ float  hbar_p[2][EDIM];
    __shared__ float  hbar_s[EDIM];
    __shared__ float  hsq_s[NH], sh_s[NH], th_s[NH], w_s[NH];
    __shared__ float  nsq_s[NNEG], sn_s[NNEG], nterm_s[NNEG];
    __shared__ float  sc_ss, sc_tt, sc_st, sc_W, sc_C, sc_P, sc_invS;

    const float4* emb4 = (const float4*)emb;
    const int sidx = s_nodes[b];
    const int tidx = t_nodes[b];

    // ---- prefetch negatives into registers: warp w owns neg w (+ 8,9 on warps 0,1) ----
    float4 negA, negB;
    negA = emb4[(size_t)n_nodes[b * NNEG + wid] * EV4 + lane];
    const bool hasB = (wid < NNEG - NWARP);    // wid < 2
    if (hasB)
        negB = emb4[(size_t)n_nodes[b * NNEG + NWARP + wid] * EV4 + lane];

    // ---- gather src/tar/his into smem (LDG.128, coalesced per row) ----
    if (wid == 0) src_s[lane] = emb4[(size_t)sidx * EV4 + lane];
    if (wid == 1) tar_s[lane] = emb4[(size_t)tidx * EV4 + lane];
    for (int h = wid; h < NH; h += NWARP)
        his_s[h][lane] = emb4[(size_t)h_nodes[b * NH + h] * EV4 + lane];
    __syncthreads();

    const float4 s4 = src_s[lane];
    const float4 t4 = tar_s[lane];

    // ---- src/tar scalars (warp 0) ----
    if (wid == 0) {
        float ss = wredsum(dot4(s4, s4));
        float tt = wredsum(dot4(t4, t4));
        float st = wredsum(dot4(s4, t4));
        if (lane == 0) { sc_ss = ss; sc_tt = tt; sc_st = st; }
    }

    // ---- per-history: h^2, s.h, t.h (each warp ~6-7 h's) ----
    for (int h = wid; h < NH; h += NWARP) {
        const float4 h4 = his_s[h][lane];
        float hh = wredsum(dot4(h4, h4));
        float sh = wredsum(dot4(s4, h4));
        float th = wredsum(dot4(t4, h4));
        if (lane == 0) { hsq_s[h] = hh; sh_s[h] = sh; th_s[h] = th; }
    }

    // ---- per-negative n^2, s.n (early; independent of softmax) ----
    {
        float nn = wredsum(dot4(negA, negA));
        float sn = wredsum(dot4(s4, negA));
        if (lane == 0) { nsq_s[wid] = nn; sn_s[wid] = sn; }
        if (hasB) {
            float nn2 = wredsum(dot4(negB, negB));
            float sn2 = wredsum(dot4(s4, negB));
            if (lane == 0) { nsq_s[NWARP + wid] = nn2; sn_s[NWARP + wid] = sn2; }
        }
    }
    __syncthreads();

    // ---- softmax + decay + weighted scalar reductions (warp 0) ----
    if (wid == 0) {
        const float src_sq = sc_ss, tar_sq = sc_tt;
        const float delta  = delta_w[sidx];
        const float ttime  = t_times[b];

        float logit[2], pal[2], dm[2];   // 2 h per lane: h = lane, lane+32
        float m = -1e30f;
#pragma unroll
        for (int k = 0; k < 2; k++) {
            const int h = lane + 32 * k;
            if (h < NH) {
                logit[k] = -(src_sq + hsq_s[h] - 2.0f * sh_s[h]);
                pal[k]   = -(tar_sq + hsq_s[h] - 2.0f * th_s[h]);
                const float dt = fabsf(ttime - h_times[b * NH + h]);
                dm[k] = expf(delta * dt) * h_mask[b * NH + h];
                m = fmaxf(m, logit[k]);
            }
        }
        m = wredmax(m);

        float S = 0.f, Wn = 0.f, Cn = 0.f, Pn = 0.f;
#pragma unroll
        for (int k = 0; k < 2; k++) {
            const int h = lane + 32 * k;
            if (h < NH) {
                const float e = expf(logit[k] - m);   // unnormalized attention
                const float w = e * dm[k];            // unnormalized weight
                w_s[h] = w;
                S  += e;
                Wn += w;
                Cn += w * hsq_s[h];
                Pn += w * pal[k];
            }
        }
        S  = wredsum(S);
        Wn = wredsum(Wn);
        Cn = wredsum(Cn);
        Pn = wredsum(Pn);
        if (lane == 0) {
            const float invS = 1.0f / S;
            sc_invS = invS;
            sc_W = Wn * invS;
            sc_C = Cn * invS;
            sc_P = Pn * invS;
        }
    }
    __syncthreads();

    // ---- hbar partials: half the threads do h 0..24, other half 25..49 ----
    {
        const int   e    = tid & (EDIM - 1);
        const int   half = tid >> 7;
        const float* hisf = (const float*)his_s;
        float acc = 0.f;
        const int h0 = half * 25;
#pragma unroll 5
        for (int h = h0; h < h0 + 25; h++)
            acc += w_s[h] * hisf[h * EDIM + e];
        hbar_p[half][e] = acc;
    }
    __syncthreads();
    if (tid < EDIM)
        hbar_s[tid] = (hbar_p[0][tid] + hbar_p[1][tid]) * sc_invS;
    __syncthreads();

    // ---- per-negative: hbar.n and log-sigmoid term ----
    {
        const float4 hb4 = ((const float4*)hbar_s)[lane];
        float hn = wredsum(dot4(hb4, negA));
        if (lane == 0) {
            const int n = wid;
            const float n_mu = -(sc_ss + nsq_s[n] - 2.0f * sn_s[n]);
            const float nl   = n_mu - sc_C - sc_W * nsq_s[n] + 2.0f * hn;
            nterm_s[n] = logf(1.0f / (1.0f + expf(nl)) + EPS);
        }
        if (hasB) {
            float hn2 = wredsum(dot4(hb4, negB));
            if (lane == 0) {
                const int n = NWARP + wid;
                const float n_mu = -(sc_ss + nsq_s[n] - 2.0f * sn_s[n]);
                const float nl   = n_mu - sc_C - sc_W * nsq_s[n] + 2.0f * hn2;
                nterm_s[n] = logf(1.0f / (1.0f + expf(nl)) + EPS);
            }
        }
    }
    __syncthreads();

    // ---- final combine ----
    if (tid == 0) {
        const float p_mu     = -(sc_ss + sc_tt - 2.0f * sc_st);
        const float p_lambda = p_mu + sc_P;
        const float pos_loss = -logf(1.0f / (1.0f + expf(-p_lambda)) + EPS);
        float neg_loss = 0.f;
#pragma unroll
        for (int n = 0; n < NNEG; n++) neg_loss += nterm_s[n];
        out[b] = pos_loss - neg_loss;
    }
}

extern "C" void kernel_launch(void* const* d_in, const int* in_sizes, int n_in,
                              void* d_out, int out_size)
{
    const int*   s_nodes = (const int*)  d_in[0];
    const int*   t_nodes = (const int*)  d_in[1];
    const float* t_times = (const float*)d_in[2];
    const int*   h_nodes = (const int*)  d_in[3];
    const float* h_times = (const float*)d_in[4];
    const float* h_mask  = (const float*)d_in[5];
    const int*   n_nodes = (const int*)  d_in[6];
    const float* emb     = (const float*)d_in[7];
    const float* delta_w = (const float*)d_in[8];
    float*       out     = (float*)d_out;

    const int B = in_sizes[0];   // 4096
    htne_kernel<<<B, NTHR>>>(s_nodes, t_nodes, t_times, h_nodes, h_times,
                             h_mask, n_nodes, emb, delta_w, out);
}

// round 4
// speedup vs baseline: 1.4086x; 1.2117x over previous
#include <cuda_runtime.h>
#include <cuda_bf16.h>

#define NTHR  256
#define NWARP 8
#define NH    50
#define NNEG  10
#define EDIM  128
#define EV4   32
#define EPS   1e-6f

__device__ __forceinline__ float dot4(float4 a, float4 b) {
    return a.x * b.x + a.y * b.y + a.z * b.z + a.w * b.w;
}

// Reduce 3 independent per-lane values across the warp with 9 shuffles.
// Result: lane 0 -> sum(a), lane 8 -> sum(b), lane 16 -> sum(c).
__device__ __forceinline__ float wred3(float a, float b, float c, int lane) {
    a += __shfl_xor_sync(0xffffffffu, a, 16);
    b += __shfl_xor_sync(0xffffffffu, b, 16);
    c += __shfl_xor_sync(0xffffffffu, c, 16);
    a += __shfl_xor_sync(0xffffffffu, a, 8);
    b += __shfl_xor_sync(0xffffffffu, b, 8);
    c += __shfl_xor_sync(0xffffffffu, c, 8);
    const int g = lane >> 3;
    float x = (g == 0) ? a : (g == 1) ? b : c;
    x += __shfl_xor_sync(0xffffffffu, x, 4);
    x += __shfl_xor_sync(0xffffffffu, x, 2);
    x += __shfl_xor_sync(0xffffffffu, x, 1);
    return x;
}

// Reduce 4 independent values with 11 shuffles.
// lane 0 -> sum(a), lane 8 -> sum(b), lane 16 -> sum(c), lane 24 -> sum(d).
__device__ __forceinline__ float wred4(float a, float b, float c, float d, int lane) {
    a += __shfl_xor_sync(0xffffffffu, a, 16);
    b += __shfl_xor_sync(0xffffffffu, b, 16);
    c += __shfl_xor_sync(0xffffffffu, c, 16);
    d += __shfl_xor_sync(0xffffffffu, d, 16);
    a += __shfl_xor_sync(0xffffffffu, a, 8);
    b += __shfl_xor_sync(0xffffffffu, b, 8);
    c += __shfl_xor_sync(0xffffffffu, c, 8);
    d += __shfl_xor_sync(0xffffffffu, d, 8);
    const int g = lane >> 3;
    float x = (g == 0) ? a : (g == 1) ? b : (g == 2) ? c : d;
    x += __shfl_xor_sync(0xffffffffu, x, 4);
    x += __shfl_xor_sync(0xffffffffu, x, 2);
    x += __shfl_xor_sync(0xffffffffu, x, 1);
    return x;
}

__device__ __forceinline__ float wredmax(float v) {
#pragma unroll
    for (int o = 16; o; o >>= 1) v = fmaxf(v, __shfl_xor_sync(0xffffffffu, v, o));
    return v;
}

__global__ __launch_bounds__(NTHR) void htne_kernel(
    const int*   __restrict__ s_nodes,   // [B,1]
    const int*   __restrict__ t_nodes,   // [B,1]
    const float* __restrict__ t_times,   // [B,1]
    const int*   __restrict__ h_nodes,   // [B,H]
    const float* __restrict__ h_times,   // [B,H]
    const float* __restrict__ h_mask,    // [B,H]
    const int*   __restrict__ n_nodes,   // [B,N]
    const float* __restrict__ emb,       // [V,E]
    const float* __restrict__ delta_w,   // [V,1]
    float*       __restrict__ out)       // [B]
{
    const int b    = blockIdx.x;
    const int tid  = threadIdx.x;
    const int wid  = tid >> 5;
    const int lane = tid & 31;

    __shared__ float his_s[NH][EDIM];    // 25.6 KB
    __shared__ float hbar_p[2][EDIM];    // 1 KB
    __shared__ float scal3[3][NH];       // 0:hh 1:sh 2:th
    __shared__ float w_s[NH];
    __shared__ float nscal[2][NNEG];     // 0:nn 1:sn
    __shared__ float nterm_s[NNEG];
    __shared__ float sc[8];              // 0:ss 1:tt 2:st 3:W 4:C 5:P 6:invS

    const float4* emb4 = (const float4*)emb;
    const int sidx = s_nodes[b];

    // ---- per-warp direct loads of src/tar (same lines -> L1 broadcast) ----
    const float4 s4 = emb4[(size_t)sidx * EV4 + lane];
    const float4 t4 = emb4[(size_t)t_nodes[b] * EV4 + lane];

    // ---- negatives into registers: warp w owns neg w (+8,9 on warps 0,1) ----
    const bool hasB = (wid < NNEG - NWARP);
    float4 negA = emb4[(size_t)n_nodes[b * NNEG + wid] * EV4 + lane];
    float4 negB = hasB ? emb4[(size_t)n_nodes[b * NNEG + NWARP + wid] * EV4 + lane]
                       : negA;

    // ---- warp 0: src/tar scalars ----
    if (wid == 0) {
        float x = wred3(dot4(s4, s4), dot4(t4, t4), dot4(s4, t4), lane);
        if ((lane & 7) == 0 && lane < 24) sc[lane >> 3] = x;   // ss, tt, st
    }

    // ---- histories: gather -> STS for later + dots from registers ----
#pragma unroll
    for (int i = 0; i < 7; i++) {
        const int h = wid + i * NWARP;
        if (h < NH) {
            const float4 h4 = emb4[(size_t)h_nodes[b * NH + h] * EV4 + lane];
            ((float4*)his_s[h])[lane] = h4;
            float x = wred3(dot4(h4, h4), dot4(s4, h4), dot4(t4, h4), lane);
            if ((lane & 7) == 0 && lane < 24) scal3[lane >> 3][h] = x;
        }
    }

    // ---- negatives: nn, sn (both A and B packed in one reduction) ----
    {
        float x = wred4(dot4(negA, negA), dot4(s4, negA),
                        dot4(negB, negB), dot4(s4, negB), lane);
        const int g = lane >> 3;
        if ((lane & 7) == 0 && (g < 2 || hasB))
            nscal[g & 1][wid + (g >> 1) * NWARP] = x;
    }
    __syncthreads();

    // ---- softmax + decay + weighted scalar reductions (warp 0) ----
    if (wid == 0) {
        const float src_sq = sc[0], tar_sq = sc[1];
        const float delta  = delta_w[sidx];
        const float ttime  = t_times[b];

        float logit[2], pal[2], dm[2];
        float m = -1e30f;
#pragma unroll
        for (int k = 0; k < 2; k++) {
            const int h = lane + 32 * k;
            if (h < NH) {
                const float hh = scal3[0][h];
                logit[k] = -(src_sq + hh - 2.0f * scal3[1][h]);
                pal[k]   = -(tar_sq + hh - 2.0f * scal3[2][h]);
                const float dt = fabsf(ttime - h_times[b * NH + h]);
                dm[k] = expf(delta * dt) * h_mask[b * NH + h];
                m = fmaxf(m, logit[k]);
            }
        }
        m = wredmax(m);

        float S = 0.f, Wn = 0.f, Cn = 0.f, Pn = 0.f;
#pragma unroll
        for (int k = 0; k < 2; k++) {
            const int h = lane + 32 * k;
            if (h < NH) {
                const float e = expf(logit[k] - m);
                const float w = e * dm[k];           // unnormalized weight
                w_s[h] = w;
                S  += e;
                Wn += w;
                Cn += w * scal3[0][h];
                Pn += w * pal[k];
            }
        }
        float x = wred4(S, Wn, Cn, Pn, lane);
        const float Sv = __shfl_sync(0xffffffffu, x, 0);
        const float Wv = __shfl_sync(0xffffffffu, x, 8);
        const float Cv = __shfl_sync(0xffffffffu, x, 16);
        const float Pv = __shfl_sync(0xffffffffu, x, 24);
        if (lane == 0) {
            const float invS = 1.0f / Sv;
            sc[3] = Wv * invS;
            sc[4] = Cv * invS;
            sc[5] = Pv * invS;
            sc[6] = invS;
        }
    }
    __syncthreads();

    // ---- hbar partials: half threads do h 0..24, other half 25..49 ----
    {
        const int e    = tid & (EDIM - 1);
        const int half = tid >> 7;
        const int h0   = half * 25;
        float acc = 0.f;
#pragma unroll 5
        for (int h = h0; h < h0 + 25; h++)
            acc += w_s[h] * his_s[h][e];
        hbar_p[half][e] = acc;
    }
    __syncthreads();

    // ---- per-negative tail: hbar.n (A and B packed), log-sigmoid term ----
    {
        const float4 p0 = ((const float4*)hbar_p[0])[lane];
        const float4 p1 = ((const float4*)hbar_p[1])[lane];
        float4 hb4;
        hb4.x = p0.x + p1.x; hb4.y = p0.y + p1.y;
        hb4.z = p0.z + p1.z; hb4.w = p0.w + p1.w;

        float hnA = dot4(hb4, negA);
        float hnB = dot4(hb4, negB);
        hnA += __shfl_xor_sync(0xffffffffu, hnA, 16);
        hnB += __shfl_xor_sync(0xffffffffu, hnB, 16);
        float x = (lane < 16) ? hnA : hnB;
        x += __shfl_xor_sync(0xffffffffu, x, 8);
        x += __shfl_xor_sync(0xffffffffu, x, 4);
        x += __shfl_xor_sync(0xffffffffu, x, 2);
        x += __shfl_xor_sync(0xffffffffu, x, 1);
        // lane 0: hnA total, lane 16: hnB total

        if (lane == 0 || (lane == 16 && hasB)) {
            const int n = wid + (lane >> 4) * NWARP;
            const float nn = nscal[0][n];
            const float sn = nscal[1][n];
            const float n_mu = -(sc[0] + nn - 2.0f * sn);
            const float nl   = n_mu - sc[4] - sc[3] * nn + 2.0f * sc[6] * x;
            nterm_s[n] = logf(1.0f / (1.0f + expf(nl)) + EPS);
        }
    }
    __syncthreads();

    // ---- final combine ----
    if (tid == 0) {
        const float p_mu     = -(sc[0] + sc[1] - 2.0f * sc[2]);
        const float p_lambda = p_mu + sc[5];
        const float pos_loss = -logf(1.0f / (1.0f + expf(-p_lambda)) + EPS);
        float neg_loss = 0.f;
#pragma unroll
        for (int n = 0; n < NNEG; n++) neg_loss += nterm_s[n];
        out[b] = pos_loss - neg_loss;
    }
}

extern "C" void kernel_launch(void* const* d_in, const int* in_sizes, int n_in,
                              void* d_out, int out_size)
{
    const int*   s_nodes = (const int*)  d_in[0];
    const int*   t_nodes = (const int*)  d_in[1];
    const float* t_times = (const float*)d_in[2];
    const int*   h_nodes = (const int*)  d_in[3];
    const float* h_times = (const float*)d_in[4];
    const float* h_mask  = (const float*)d_in[5];
    const int*   n_nodes = (const int*)  d_in[6];
    const float* emb     = (const float*)d_in[7];
    const float* delta_w = (const float*)d_in[8];
    float*       out     = (float*)d_out;

    const int B = in_sizes[0];   // 4096
    htne_kernel<<<B, NTHR>>>(s_nodes, t_nodes, t_times, h_nodes, h_times,
                             h_mask, n_nodes, emb, delta_w, out);
}

// round 5
// speedup vs baseline: 1.4873x; 1.0559x over previous
#include <cuda_runtime.h>
#include <cuda_bf16.h>

#define NTHR  256
#define NWARP 8
#define NH    50
#define NNEG  10
#define NROWS 62
#define EDIM  128
#define EV4   32
#define EPS   1e-6f

__device__ __forceinline__ float dot4(float4 a, float4 b) {
    return a.x * b.x + a.y * b.y + a.z * b.z + a.w * b.w;
}
__device__ __forceinline__ float wredsum(float v) {
#pragma unroll
    for (int o = 16; o; o >>= 1) v += __shfl_xor_sync(0xffffffffu, v, o);
    return v;
}
__device__ __forceinline__ float wredmax(float v) {
#pragma unroll
    for (int o = 16; o; o >>= 1) v = fmaxf(v, __shfl_xor_sync(0xffffffffu, v, o));
    return v;
}

__global__ __launch_bounds__(NTHR, 6) void htne_kernel(
    const int*   __restrict__ s_nodes,
    const int*   __restrict__ t_nodes,
    const float* __restrict__ t_times,
    const int*   __restrict__ h_nodes,
    const float* __restrict__ h_times,
    const float* __restrict__ h_mask,
    const int*   __restrict__ n_nodes,
    const float* __restrict__ emb,
    const float* __restrict__ delta_w,
    float*       __restrict__ out)
{
    const int b    = blockIdx.x;
    const int tid  = threadIdx.x;
    const int wid  = tid >> 5;
    const int lane = tid & 31;

    __shared__ float his_s[NH][EDIM];
    __shared__ float hbar_p[2][EDIM];
    __shared__ float scal_s[64 * 4];     // [row][0:rr 1:rs 2:rt]
    __shared__ float w_s[NH];
    __shared__ float nterm_s[NNEG];
    __shared__ float sc[4];              // 0:W 1:C 2:P 3:invS

    const float4* emb4 = (const float4*)emb;
    const int sidx = s_nodes[b];
    const int tidx = t_nodes[b];

    const int sub     = lane & 15;
    const int halfsel = lane >> 4;

    const float4 s4a = emb4[(size_t)sidx * EV4 + sub];
    const float4 s4b = emb4[(size_t)sidx * EV4 + sub + 16];
    const float4 t4a = emb4[(size_t)tidx * EV4 + sub];
    const float4 t4b = emb4[(size_t)tidx * EV4 + sub + 16];

    // ---- phase 1: uniform 62-row gather + dots, 8 shfl per 2 rows ----
#pragma unroll
    for (int j = 0; j < 4; j++) {
        const int r = j * 16 + wid * 2 + halfsel;
        int node;
        if      (r < NH)  node = h_nodes[b * NH + r];
        else if (r < 60)  node = n_nodes[b * NNEG + (r - 50)];
        else if (r == 60) node = sidx;
        else              node = tidx;
        const float4* rowp = emb4 + (size_t)node * EV4;
        const float4 r0 = rowp[sub];
        const float4 r1 = rowp[sub + 16];
        if (r < NH) {
            float4* hs = (float4*)his_s[r];
            hs[sub]      = r0;
            hs[sub + 16] = r1;
        }
        float a  = dot4(r0, r0)  + dot4(r1, r1);
        float bb = dot4(r0, s4a) + dot4(r1, s4b);
        float c  = dot4(r0, t4a) + dot4(r1, t4b);
        a  += __shfl_xor_sync(0xffffffffu, a, 8);
        bb += __shfl_xor_sync(0xffffffffu, bb, 8);
        c  += __shfl_xor_sync(0xffffffffu, c, 8);
        a  += __shfl_xor_sync(0xffffffffu, a, 4);
        bb += __shfl_xor_sync(0xffffffffu, bb, 4);
        c  += __shfl_xor_sync(0xffffffffu, c, 4);
        const int g2 = (lane >> 2) & 3;
        float x = (g2 == 0) ? a : (g2 == 1) ? bb : c;
        x += __shfl_xor_sync(0xffffffffu, x, 2);
        x += __shfl_xor_sync(0xffffffffu, x, 1);
        if ((lane & 3) == 0 && g2 < 3 && r < NROWS)
            scal_s[r * 4 + g2] = x;
    }
    __syncthreads();

    // ---- softmax + weighted scalar reductions (warp 0) ----
    if (wid == 0) {
        const float src_sq = scal_s[60 * 4 + 0];
        const float tar_sq = scal_s[61 * 4 + 0];
        const float delta  = delta_w[sidx];
        const float ttime  = t_times[b];

        float logit[2], pal[2], dm[2];
        float m = -1e30f;
#pragma unroll
        for (int k = 0; k < 2; k++) {
            const int h = lane + 32 * k;
            if (h < NH) {
                const float hh = scal_s[h * 4 + 0];
                logit[k] = -(src_sq + hh - 2.0f * scal_s[h * 4 + 1]);
                pal[k]   = -(tar_sq + hh - 2.0f * scal_s[h * 4 + 2]);
                const float dt = fabsf(ttime - h_times[b * NH + h]);
                dm[k] = __expf(delta * dt) * h_mask[b * NH + h];
                m = fmaxf(m, logit[k]);
            }
        }
        m = wredmax(m);

        float S = 0.f, Wn = 0.f, Cn = 0.f, Pn = 0.f;
#pragma unroll
        for (int k = 0; k < 2; k++) {
            const int h = lane + 32 * k;
            if (h < NH) {
                const float e = __expf(logit[k] - m);
                const float w = e * dm[k];
                w_s[h] = w;
                S  += e;
                Wn += w;
                Cn += w * scal_s[h * 4 + 0];
                Pn += w * pal[k];
            }
        }
        S  += __shfl_xor_sync(0xffffffffu, S, 16);
        Wn += __shfl_xor_sync(0xffffffffu, Wn, 16);
        Cn += __shfl_xor_sync(0xffffffffu, Cn, 16);
        Pn += __shfl_xor_sync(0xffffffffu, Pn, 16);
        S  += __shfl_xor_sync(0xffffffffu, S, 8);
        Wn += __shfl_xor_sync(0xffffffffu, Wn, 8);
        Cn += __shfl_xor_sync(0xffffffffu, Cn, 8);
        Pn += __shfl_xor_sync(0xffffffffu, Pn, 8);
        const int g = lane >> 3;
        float x = (g == 0) ? S : (g == 1) ? Wn : (g == 2) ? Cn : Pn;
        x += __shfl_xor_sync(0xffffffffu, x, 4);
        x += __shfl_xor_sync(0xffffffffu, x, 2);
        x += __shfl_xor_sync(0xffffffffu, x, 1);
        const float Sv = __shfl_sync(0xffffffffu, x, 0);
        if (lane == 8)  sc[0] = x / Sv;      // W
        if (lane == 16) sc[1] = x / Sv;      // C
        if (lane == 24) sc[2] = x / Sv;      // P
        if (lane == 0)  sc[3] = 1.0f / Sv;   // invS
    }
    __syncthreads();

    // ---- hbar partials ----
    {
        const int e    = tid & (EDIM - 1);
        const int half = tid >> 7;
        const int h0   = half * 25;
        float acc = 0.f;
#pragma unroll 5
        for (int h = h0; h < h0 + 25; h++)
            acc += w_s[h] * his_s[h][e];
        hbar_p[half][e] = acc;
    }
    __syncthreads();

    // ---- tail: per-negative hbar.n (reload neg rows, L1/L2-hot) ----
    {
        const float4 p0 = ((const float4*)hbar_p[0])[lane];
        const float4 p1 = ((const float4*)hbar_p[1])[lane];
        float4 hb4;
        hb4.x = p0.x + p1.x; hb4.y = p0.y + p1.y;
        hb4.z = p0.z + p1.z; hb4.w = p0.w + p1.w;

        const float Wv = sc[0], Cv = sc[1], invS = sc[3];
        const float ss = scal_s[60 * 4 + 0];

        {
            const int n = wid;
            const float4 ng = emb4[(size_t)n_nodes[b * NNEG + n] * EV4 + lane];
            float hn = wredsum(dot4(hb4, ng));
            if (lane == 0) {
                const float nn = scal_s[(50 + n) * 4 + 0];
                const float sn = scal_s[(50 + n) * 4 + 1];
                const float n_mu = -(ss + nn - 2.0f * sn);
                const float nl   = n_mu - Cv - Wv * nn + 2.0f * invS * hn;
                nterm_s[n] = __logf(1.0f / (1.0f + __expf(nl)) + EPS);
            }
        }
        if (wid < NNEG - NWARP) {
            const int n = NWARP + wid;
            const float4 ng = emb4[(size_t)n_nodes[b * NNEG + n] * EV4 + lane];
            float hn = wredsum(dot4(hb4, ng));
            if (lane == 0) {
                const float nn = scal_s[(50 + n) * 4 + 0];
                const float sn = scal_s[(50 + n) * 4 + 1];
                const float n_mu = -(ss + nn - 2.0f * sn);
                const float nl   = n_mu - Cv - Wv * nn + 2.0f * invS * hn;
                nterm_s[n] = __logf(1.0f / (1.0f + __expf(nl)) + EPS);
            }
        }
    }
    __syncthreads();

    if (tid == 0) {
        const float ss = scal_s[60 * 4 + 0];
        const float st = scal_s[60 * 4 + 2];
        const float tt = scal_s[61 * 4 + 0];
        const float p_mu     = -(ss + tt - 2.0f * st);
        const float p_lambda = p_mu + sc[2];
        const float pos_loss = -__logf(1.0f / (1.0f + __expf(-p_lambda)) + EPS);
        float neg_loss = 0.f;
#pragma unroll
        for (int n = 0; n < NNEG; n++) neg_loss += nterm_s[n];
        out[b] = pos_loss - neg_loss;
    }
}

extern "C" void kernel_launch(void* const* d_in, const int* in_sizes, int n_in,
                              void* d_out, int out_size)
{
    const int*   s_nodes = (const int*)  d_in[0];
    const int*   t_nodes = (const int*)  d_in[1];
    const float* t_times = (const float*)d_in[2];
    const int*   h_nodes = (const int*)  d_in[3];
    const float* h_times = (const float*)d_in[4];
    const float* h_mask  = (const float*)d_in[5];
    const int*   n_nodes = (const int*)  d_in[6];
    const float* emb     = (const float*)d_in[7];
    const float* delta_w = (const float*)d_in[8];
    float*       out     = (float*)d_out;

    const int B = in_sizes[0];
    htne_kernel<<<B, NTHR>>>(s_nodes, t_nodes, t_times, h_nodes, h_times,
                             h_mask, n_nodes, emb, delta_w, out);
}